// round 6
// baseline (speedup 1.0000x reference)
#include <cuda_runtime.h>
#include <cstdint>

#define N_SRC 50000
#define N_DST 50000
#define IN_FEAT 128
#define OUT_FEAT 128
#define MAX_EDGES 600000

// ---------------------------------------------------------------------------
// Device-global scratch (allocation-free).
// ---------------------------------------------------------------------------
__device__ float g_neigh[(size_t)N_DST * IN_FEAT];  // mean-aggregated
__device__ int   g_cnt[N_DST];
__device__ int   g_offs[N_DST + 1];
__device__ int   g_cursor[N_DST];
__device__ int   g_csr[MAX_EDGES];

// ---------------------------------------------------------------------------
// 1) zero per-dst counters (g_neigh needs no zeroing: agg writes every row)
// ---------------------------------------------------------------------------
__global__ __launch_bounds__(256) void zero_cnt_kernel() {
    int i = blockIdx.x * blockDim.x + threadIdx.x;
    if (i < N_DST) g_cnt[i] = 0;
}

// ---------------------------------------------------------------------------
// 2) histogram of dst
// ---------------------------------------------------------------------------
__global__ __launch_bounds__(256) void hist_kernel(const int* __restrict__ dst, int n_edges) {
    int i = blockIdx.x * blockDim.x + threadIdx.x;
    if (i < n_edges) atomicAdd(&g_cnt[__ldg(dst + i)], 1);
}

// ---------------------------------------------------------------------------
// 3) exclusive scan over 50K counts (single block, ~4us of real work)
// ---------------------------------------------------------------------------
#define SCAN_THREADS 1024
__global__ __launch_bounds__(SCAN_THREADS) void scan_kernel() {
    __shared__ int part[SCAN_THREADS];
    const int t = threadIdx.x;
    const int CH = (N_DST + SCAN_THREADS - 1) / SCAN_THREADS;   // 49
    int beg = t * CH;
    int end = min(beg + CH, N_DST);
    int s = 0;
    #pragma unroll 7
    for (int i = beg; i < end; ++i) s += g_cnt[i];
    part[t] = s;
    __syncthreads();
    for (int off = 1; off < SCAN_THREADS; off <<= 1) {
        int v = (t >= off) ? part[t - off] : 0;
        __syncthreads();
        part[t] += v;
        __syncthreads();
    }
    int run = (t == 0) ? 0 : part[t - 1];
    for (int i = beg; i < end; ++i) {
        g_offs[i] = run;
        g_cursor[i] = run;
        run += g_cnt[i];
    }
    if (t == SCAN_THREADS - 1) g_offs[N_DST] = run;
}

// ---------------------------------------------------------------------------
// 4) scatter src ids into CSR buckets (2 edges/thread for ILP)
// ---------------------------------------------------------------------------
__global__ __launch_bounds__(256) void scatter_kernel(
    const int* __restrict__ src, const int* __restrict__ dst, int n_edges)
{
    int base = (blockIdx.x * blockDim.x + threadIdx.x) * 2;
    #pragma unroll
    for (int j = 0; j < 2; ++j) {
        int i = base + j;
        if (i < n_edges) {
            int d = __ldg(dst + i);
            int s = __ldg(src + i);
            int pos = atomicAdd(&g_cursor[d], 1);
            g_csr[pos] = s;
        }
    }
}

// ---------------------------------------------------------------------------
// 5) aggregation: one warp per dst, 4-way unrolled gather, mean folded in.
// ---------------------------------------------------------------------------
__global__ __launch_bounds__(256) void agg_kernel(const float* __restrict__ h_s) {
    int w    = (blockIdx.x * blockDim.x + threadIdx.x) >> 5;
    int lane = threadIdx.x & 31;
    if (w >= N_DST) return;

    int beg = __ldg(g_offs + w);
    int end = __ldg(g_offs + w + 1);

    float4 acc = make_float4(0.f, 0.f, 0.f, 0.f);
    const float4* hs4 = reinterpret_cast<const float4*>(h_s);

    int e = beg;
    for (; e + 3 < end; e += 4) {
        int s0 = __ldg(g_csr + e);
        int s1 = __ldg(g_csr + e + 1);
        int s2 = __ldg(g_csr + e + 2);
        int s3 = __ldg(g_csr + e + 3);
        float4 v0 = __ldg(hs4 + (size_t)s0 * 32 + lane);
        float4 v1 = __ldg(hs4 + (size_t)s1 * 32 + lane);
        float4 v2 = __ldg(hs4 + (size_t)s2 * 32 + lane);
        float4 v3 = __ldg(hs4 + (size_t)s3 * 32 + lane);
        acc.x += (v0.x + v1.x) + (v2.x + v3.x);
        acc.y += (v0.y + v1.y) + (v2.y + v3.y);
        acc.z += (v0.z + v1.z) + (v2.z + v3.z);
        acc.w += (v0.w + v1.w) + (v2.w + v3.w);
    }
    for (; e < end; ++e) {
        int s0 = __ldg(g_csr + e);
        float4 v0 = __ldg(hs4 + (size_t)s0 * 32 + lane);
        acc.x += v0.x; acc.y += v0.y; acc.z += v0.z; acc.w += v0.w;
    }

    float inv = 1.f / fmaxf((float)(end - beg), 1.f);
    acc.x *= inv; acc.y *= inv; acc.z *= inv; acc.w *= inv;
    reinterpret_cast<float4*>(g_neigh)[(size_t)w * 32 + lane] = acc;
}

// ---------------------------------------------------------------------------
// 6) fused concat + Linear via TF32 mma.sync + ldmatrix (unchanged from R5,
//    minus the sInv path — mean is already applied).
// ---------------------------------------------------------------------------
#define BM 128
#define BK 32
#define KPAD 36   // 144B row stride = 9x16B units -> LDSM rows distinct mod 8

__device__ __forceinline__ uint32_t f2tf32(float v) {
    uint32_t r;
    asm("cvt.rna.tf32.f32 %0, %1;" : "=r"(r) : "f"(v));
    return r;
}

__device__ __forceinline__ void mma_tf32(float c[4],
                                         uint32_t a0, uint32_t a1, uint32_t a2, uint32_t a3,
                                         uint32_t b0, uint32_t b1) {
    asm("mma.sync.aligned.m16n8k8.row.col.f32.tf32.tf32.f32 "
        "{%0,%1,%2,%3}, {%4,%5,%6,%7}, {%8,%9}, {%0,%1,%2,%3};"
        : "+f"(c[0]), "+f"(c[1]), "+f"(c[2]), "+f"(c[3])
        : "r"(a0), "r"(a1), "r"(a2), "r"(a3), "r"(b0), "r"(b1));
}

#define LDSM_X4(r0, r1, r2, r3, addr) \
    asm volatile("ldmatrix.sync.aligned.m8n8.x4.shared.b16 {%0,%1,%2,%3}, [%4];" \
                 : "=r"(r0), "=r"(r1), "=r"(r2), "=r"(r3) : "r"(addr))

__global__ __launch_bounds__(256) void gemm_kernel(
    const float* __restrict__ h_d,
    const float* __restrict__ W,     // [128, 256] row-major
    const float* __restrict__ bias,  // [128]
    float* __restrict__ out)         // [N_DST, 128]
{
    __shared__ uint32_t As[BM][KPAD];        // [m][k] tf32
    __shared__ uint32_t Bs[OUT_FEAT][KPAD];  // [n][k] tf32

    const int t    = threadIdx.x;
    const int bm   = blockIdx.x * BM;
    const int wid  = t >> 5;
    const int lane = t & 31;
    const int warp_m = wid >> 1;   // 0..3
    const int warp_n = wid & 1;    // 0..1
    const int group  = lane >> 2;  // 0..7
    const int tid4   = lane & 3;   // 0..3

    // ldmatrix per-thread row addresses
    const int lrow = lane & 7;
    const int lmat = lane >> 3;
    uint32_t as_base = (uint32_t)__cvta_generic_to_shared(&As[0][0]);
    uint32_t bs_base = (uint32_t)__cvta_generic_to_shared(&Bs[0][0]);

    uint32_t aAddr[2];
    #pragma unroll
    for (int mt = 0; mt < 2; ++mt) {
        int row = warp_m * 32 + mt * 16 + (lmat & 1) * 8 + lrow;
        int col = (lmat >> 1) * 4;
        aAddr[mt] = as_base + (row * KPAD + col) * 4;
    }
    uint32_t bAddr[4];
    #pragma unroll
    for (int p = 0; p < 4; ++p) {
        int row = warp_n * 64 + p * 16 + (lmat >> 1) * 8 + lrow;
        int col = (lmat & 1) * 4;
        bAddr[p] = bs_base + (row * KPAD + col) * 4;
    }

    float acc[2][8][4];
    #pragma unroll
    for (int mt = 0; mt < 2; ++mt)
        #pragma unroll
        for (int nt = 0; nt < 8; ++nt)
            #pragma unroll
            for (int c = 0; c < 4; ++c) acc[mt][nt][c] = 0.f;

    #pragma unroll 1
    for (int ph = 0; ph < 2; ++ph) {
        const float* __restrict__ A = ph ? g_neigh : h_d;
        #pragma unroll 1
        for (int k0 = 0; k0 < IN_FEAT; k0 += BK) {
            __syncthreads();

            #pragma unroll
            for (int i = 0; i < 4; ++i) {
                int idx = t + i * 256;
                int row = idx >> 3;
                int c4  = (idx & 7) * 4;
                int gr  = bm + row;
                float4 v = make_float4(0.f, 0.f, 0.f, 0.f);
                if (gr < N_DST)
                    v = __ldg(reinterpret_cast<const float4*>(A + (size_t)gr * IN_FEAT + k0 + c4));
                As[row][c4 + 0] = f2tf32(v.x);
                As[row][c4 + 1] = f2tf32(v.y);
                As[row][c4 + 2] = f2tf32(v.z);
                As[row][c4 + 3] = f2tf32(v.w);
            }
            #pragma unroll
            for (int i = 0; i < 4; ++i) {
                int idx = t + i * 256;
                int o   = idx >> 3;
                int c4  = (idx & 7) * 4;
                float4 v = __ldg(reinterpret_cast<const float4*>(
                    W + (size_t)o * (2 * IN_FEAT) + ph * IN_FEAT + k0 + c4));
                Bs[o][c4 + 0] = f2tf32(v.x);
                Bs[o][c4 + 1] = f2tf32(v.y);
                Bs[o][c4 + 2] = f2tf32(v.z);
                Bs[o][c4 + 3] = f2tf32(v.w);
            }
            __syncthreads();

            #pragma unroll
            for (int kk = 0; kk < BK; kk += 8) {
                uint32_t af[2][4], bf[8][2];
                #pragma unroll
                for (int mt = 0; mt < 2; ++mt)
                    LDSM_X4(af[mt][0], af[mt][1], af[mt][2], af[mt][3],
                            aAddr[mt] + kk * 4);
                #pragma unroll
                for (int p = 0; p < 4; ++p)
                    LDSM_X4(bf[2 * p][0], bf[2 * p][1], bf[2 * p + 1][0], bf[2 * p + 1][1],
                            bAddr[p] + kk * 4);
                #pragma unroll
                for (int mt = 0; mt < 2; ++mt)
                    #pragma unroll
                    for (int nt = 0; nt < 8; ++nt)
                        mma_tf32(acc[mt][nt], af[mt][0], af[mt][1], af[mt][2], af[mt][3],
                                 bf[nt][0], bf[nt][1]);
            }
        }
    }

    #pragma unroll
    for (int mt = 0; mt < 2; ++mt) {
        int r0 = bm + warp_m * 32 + mt * 16 + group;
        #pragma unroll
        for (int nt = 0; nt < 8; ++nt) {
            int c = warp_n * 64 + nt * 8 + tid4 * 2;
            float b0 = __ldg(bias + c);
            float b1 = __ldg(bias + c + 1);
            if (r0 < N_DST) {
                float2 v = make_float2(acc[mt][nt][0] + b0, acc[mt][nt][1] + b1);
                *reinterpret_cast<float2*>(out + (size_t)r0 * OUT_FEAT + c) = v;
            }
            int r1 = r0 + 8;
            if (r1 < N_DST) {
                float2 v = make_float2(acc[mt][nt][2] + b0, acc[mt][nt][3] + b1);
                *reinterpret_cast<float2*>(out + (size_t)r1 * OUT_FEAT + c) = v;
            }
        }
    }
}

// ---------------------------------------------------------------------------
extern "C" void kernel_launch(void* const* d_in, const int* in_sizes, int n_in,
                              void* d_out, int out_size)
{
    const float* h_s = (const float*)d_in[0];
    const float* h_d = (const float*)d_in[1];
    const int*   src = (const int*)d_in[2];
    const int*   dst = (const int*)d_in[3];
    const float* W   = (const float*)d_in[4];
    const float* b   = (const float*)d_in[5];
    float* out = (float*)d_out;

    const int n_edges = in_sizes[2];

    zero_cnt_kernel<<<(N_DST + 255) / 256, 256>>>();
    hist_kernel<<<(n_edges + 255) / 256, 256>>>(dst, n_edges);
    scan_kernel<<<1, SCAN_THREADS>>>();
    scatter_kernel<<<(n_edges / 2 + 255) / 256, 256>>>(src, dst, n_edges);
    agg_kernel<<<(N_DST * 32 + 255) / 256, 256>>>(h_s);

    int gblocks = (N_DST + BM - 1) / BM;              // 391
    gemm_kernel<<<gblocks, 256>>>(h_d, W, b, out);
}

// round 7
// speedup vs baseline: 1.4708x; 1.4708x over previous
#include <cuda_runtime.h>
#include <cstdint>

#define N_SRC 50000
#define N_DST 50000
#define IN_FEAT 128
#define OUT_FEAT 128

// Device-global scratch (allocation-free).
__device__ float g_neigh[(size_t)N_DST * IN_FEAT];
__device__ float g_deg[N_DST];

// ---------------------------------------------------------------------------
// Kernel 1: zero the accumulators
// ---------------------------------------------------------------------------
__global__ __launch_bounds__(256) void zero_kernel() {
    const size_t n4 = (size_t)N_DST * IN_FEAT / 4;
    size_t i = (size_t)blockIdx.x * blockDim.x + threadIdx.x;
    size_t stride = (size_t)gridDim.x * blockDim.x;
    float4* p = reinterpret_cast<float4*>(g_neigh);
    for (size_t j = i; j < n4; j += stride)
        p[j] = make_float4(0.f, 0.f, 0.f, 0.f);
    for (size_t j = i; j < N_DST; j += stride)
        g_deg[j] = 0.f;
}

// ---------------------------------------------------------------------------
// Kernel 2: edge aggregation. 4 edges per warp: batch the index loads and
// gathers (MLP=4) before the reductions. REDG lane count unchanged (floor).
// ---------------------------------------------------------------------------
#define EPW 4
__global__ __launch_bounds__(256) void edge_kernel(
    const float* __restrict__ h_s,
    const int* __restrict__ src,
    const int* __restrict__ dst,
    int n_edges)
{
    int warp = (blockIdx.x * blockDim.x + threadIdx.x) >> 5;
    int lane = threadIdx.x & 31;
    int e0 = warp * EPW;
    if (e0 >= n_edges) return;
    int n = min(EPW, n_edges - e0);

    const float4* hs4 = reinterpret_cast<const float4*>(h_s);

    int s[EPW], d[EPW];
    #pragma unroll
    for (int j = 0; j < EPW; ++j) {
        if (j < n) {
            s[j] = __ldg(src + e0 + j);
            d[j] = __ldg(dst + e0 + j);
        }
    }
    float4 v[EPW];
    #pragma unroll
    for (int j = 0; j < EPW; ++j)
        if (j < n) v[j] = __ldg(hs4 + (size_t)s[j] * 32 + lane);

    #pragma unroll
    for (int j = 0; j < EPW; ++j) {
        if (j < n) {
            float* p = g_neigh + (size_t)d[j] * IN_FEAT + lane * 4;
            asm volatile("red.global.add.v4.f32 [%0], {%1, %2, %3, %4};"
                         :: "l"(p), "f"(v[j].x), "f"(v[j].y), "f"(v[j].z), "f"(v[j].w)
                         : "memory");
        }
    }
    if (lane == 0) {
        #pragma unroll
        for (int j = 0; j < EPW; ++j)
            if (j < n) atomicAdd(g_deg + d[j], 1.0f);
    }
}

// ---------------------------------------------------------------------------
// Kernel 3: fused mean + concat + Linear. TF32 mma.sync + ldmatrix,
// register double-buffered software pipeline, ONE __syncthreads per k-iter.
// ---------------------------------------------------------------------------
#define BM 128
#define BK 32
#define KPAD 36                     // 9x16B row stride -> LDSM conflict-free
#define TILE_WORDS (BM * KPAD)      // 4608 words = 18432 B per tile
#define SMEM_BYTES (4 * TILE_WORDS * 4)   // As0,As1,Bs0,Bs1 = 73728 B

__device__ __forceinline__ uint32_t f2tf32(float v) {
    uint32_t r;
    asm("cvt.rna.tf32.f32 %0, %1;" : "=r"(r) : "f"(v));
    return r;
}

__device__ __forceinline__ void mma_tf32(float c[4],
                                         uint32_t a0, uint32_t a1, uint32_t a2, uint32_t a3,
                                         uint32_t b0, uint32_t b1) {
    asm("mma.sync.aligned.m16n8k8.row.col.f32.tf32.tf32.f32 "
        "{%0,%1,%2,%3}, {%4,%5,%6,%7}, {%8,%9}, {%0,%1,%2,%3};"
        : "+f"(c[0]), "+f"(c[1]), "+f"(c[2]), "+f"(c[3])
        : "r"(a0), "r"(a1), "r"(a2), "r"(a3), "r"(b0), "r"(b1));
}

#define LDSM_X4(r0, r1, r2, r3, addr) \
    asm volatile("ldmatrix.sync.aligned.m8n8.x4.shared.b16 {%0,%1,%2,%3}, [%4];" \
                 : "=r"(r0), "=r"(r1), "=r"(r2), "=r"(r3) : "r"(addr))

__global__ __launch_bounds__(256) void gemm_kernel(
    const float* __restrict__ h_d,
    const float* __restrict__ W,     // [128, 256] row-major
    const float* __restrict__ bias,  // [128]
    float* __restrict__ out)         // [N_DST, 128]
{
    extern __shared__ uint32_t smem[];
    uint32_t* AsBuf[2] = { smem,                 smem + TILE_WORDS };
    uint32_t* BsBuf[2] = { smem + 2 * TILE_WORDS, smem + 3 * TILE_WORDS };
    __shared__ float sInv[BM];

    const int t    = threadIdx.x;
    const int bm   = blockIdx.x * BM;
    const int wid  = t >> 5;
    const int lane = t & 31;
    const int warp_m = wid >> 1;
    const int warp_n = wid & 1;
    const int group  = lane >> 2;
    const int tid4   = lane & 3;

    if (t < BM) {
        int r = bm + t;
        float dg = (r < N_DST) ? g_deg[r] : 1.0f;
        sInv[t] = 1.0f / fmaxf(dg, 1.0f);
    }

    // per-thread load coordinates (same for A and B tiles)
    const int ld_row = t >> 3;             // 0..31 row pairs? no: with 4 chunks below
    const int ld_c4  = (t & 7) * 4;        // 0..28

    // ldmatrix base addresses (buffer 0); buffer 1 = +TILE_WORDS*4 bytes
    const int lrow = lane & 7;
    const int lmat = lane >> 3;
    uint32_t as_base = (uint32_t)__cvta_generic_to_shared(AsBuf[0]);
    uint32_t bs_base = (uint32_t)__cvta_generic_to_shared(BsBuf[0]);
    const uint32_t bufstep = TILE_WORDS * 4;

    uint32_t aAddr[2];
    #pragma unroll
    for (int mt = 0; mt < 2; ++mt) {
        int row = warp_m * 32 + mt * 16 + (lmat & 1) * 8 + lrow;
        int col = (lmat >> 1) * 4;
        aAddr[mt] = as_base + (row * KPAD + col) * 4;
    }
    uint32_t bAddr[4];
    #pragma unroll
    for (int p = 0; p < 4; ++p) {
        int row = warp_n * 64 + p * 16 + (lmat >> 1) * 8 + lrow;
        int col = (lmat & 1) * 4;
        bAddr[p] = bs_base + (row * KPAD + col) * 4;
    }

    float acc[2][8][4];
    #pragma unroll
    for (int mt = 0; mt < 2; ++mt)
        #pragma unroll
        for (int nt = 0; nt < 8; ++nt)
            #pragma unroll
            for (int c = 0; c < 4; ++c) acc[mt][nt][c] = 0.f;

    // ---- tile loaders ----
    auto ldg_tile = [&](int it, float4 av[4], float4 bv[4]) {
        int ph = it >> 2;
        int k0 = (it & 3) * BK;
        const float* __restrict__ A = ph ? g_neigh : h_d;
        #pragma unroll
        for (int i = 0; i < 4; ++i) {
            int row = ld_row + i * 32;          // 0..127
            int gr  = bm + row;
            av[i] = make_float4(0.f, 0.f, 0.f, 0.f);
            if (gr < N_DST)
                av[i] = __ldg(reinterpret_cast<const float4*>(A + (size_t)gr * IN_FEAT + k0 + ld_c4));
        }
        #pragma unroll
        for (int i = 0; i < 4; ++i) {
            int o = ld_row + i * 32;
            bv[i] = __ldg(reinterpret_cast<const float4*>(
                W + (size_t)o * (2 * IN_FEAT) + ph * IN_FEAT + k0 + ld_c4));
        }
    };
    auto sts_tile = [&](int it, const float4 av[4], const float4 bv[4]) {
        int ph = it >> 2;
        uint32_t* As = AsBuf[it & 1];
        uint32_t* Bs = BsBuf[it & 1];
        #pragma unroll
        for (int i = 0; i < 4; ++i) {
            int row = ld_row + i * 32;
            float s = ph ? sInv[row] : 1.0f;
            uint32_t* p = As + row * KPAD + ld_c4;
            p[0] = f2tf32(av[i].x * s);
            p[1] = f2tf32(av[i].y * s);
            p[2] = f2tf32(av[i].z * s);
            p[3] = f2tf32(av[i].w * s);
        }
        #pragma unroll
        for (int i = 0; i < 4; ++i) {
            int o = ld_row + i * 32;
            uint32_t* p = Bs + o * KPAD + ld_c4;
            p[0] = f2tf32(bv[i].x);
            p[1] = f2tf32(bv[i].y);
            p[2] = f2tf32(bv[i].z);
            p[3] = f2tf32(bv[i].w);
        }
    };

    // ---- prologue: tile 0 ----
    {
        float4 av[4], bv[4];
        ldg_tile(0, av, bv);
        __syncthreads();            // sInv ready before sts (ph0 doesn't use it, but cheap)
        sts_tile(0, av, bv);
        __syncthreads();
    }

    // ---- main pipeline: 8 iterations, one sync each ----
    #pragma unroll 1
    for (int it = 0; it < 8; ++it) {
        float4 av[4], bv[4];
        if (it < 7) ldg_tile(it + 1, av, bv);   // overlap with compute below

        uint32_t boff = (it & 1) * bufstep;
        #pragma unroll
        for (int kk = 0; kk < BK; kk += 8) {
            uint32_t af[2][4], bf[8][2];
            #pragma unroll
            for (int mt = 0; mt < 2; ++mt)
                LDSM_X4(af[mt][0], af[mt][1], af[mt][2], af[mt][3],
                        aAddr[mt] + boff + kk * 4);
            #pragma unroll
            for (int p = 0; p < 4; ++p)
                LDSM_X4(bf[2 * p][0], bf[2 * p][1], bf[2 * p + 1][0], bf[2 * p + 1][1],
                        bAddr[p] + boff + kk * 4);
            #pragma unroll
            for (int mt = 0; mt < 2; ++mt)
                #pragma unroll
                for (int nt = 0; nt < 8; ++nt)
                    mma_tf32(acc[mt][nt], af[mt][0], af[mt][1], af[mt][2], af[mt][3],
                             bf[nt][0], bf[nt][1]);
        }

        if (it < 7) {
            sts_tile(it + 1, av, bv);   // writes buf[(it+1)&1]; last read at it-1, ordered by prev sync
            __syncthreads();
        }
    }

    // ---- epilogue: bias + store ----
    #pragma unroll
    for (int mt = 0; mt < 2; ++mt) {
        int r0 = bm + warp_m * 32 + mt * 16 + group;
        #pragma unroll
        for (int nt = 0; nt < 8; ++nt) {
            int c = warp_n * 64 + nt * 8 + tid4 * 2;
            float b0 = __ldg(bias + c);
            float b1 = __ldg(bias + c + 1);
            if (r0 < N_DST) {
                float2 v = make_float2(acc[mt][nt][0] + b0, acc[mt][nt][1] + b1);
                *reinterpret_cast<float2*>(out + (size_t)r0 * OUT_FEAT + c) = v;
            }
            int r1 = r0 + 8;
            if (r1 < N_DST) {
                float2 v = make_float2(acc[mt][nt][2] + b0, acc[mt][nt][3] + b1);
                *reinterpret_cast<float2*>(out + (size_t)r1 * OUT_FEAT + c) = v;
            }
        }
    }
}

// ---------------------------------------------------------------------------
extern "C" void kernel_launch(void* const* d_in, const int* in_sizes, int n_in,
                              void* d_out, int out_size)
{
    const float* h_s = (const float*)d_in[0];
    const float* h_d = (const float*)d_in[1];
    const int*   src = (const int*)d_in[2];
    const int*   dst = (const int*)d_in[3];
    const float* W   = (const float*)d_in[4];
    const float* b   = (const float*)d_in[5];
    float* out = (float*)d_out;

    const int n_edges = in_sizes[2];

    // Host-side attribute set: runs during capture only, zero replay cost.
    cudaFuncSetAttribute(gemm_kernel,
                         cudaFuncAttributeMaxDynamicSharedMemorySize, SMEM_BYTES);

    zero_kernel<<<2960, 256>>>();

    int warps = (n_edges + EPW - 1) / EPW;
    int blocks = (warps * 32 + 255) / 256;
    edge_kernel<<<blocks, 256>>>(h_s, src, dst, n_edges);

    int gblocks = (N_DST + BM - 1) / BM;              // 391
    gemm_kernel<<<gblocks, 256, SMEM_BYTES>>>(h_d, W, b, out);
}

// round 9
// speedup vs baseline: 1.6459x; 1.1191x over previous
#include <cuda_runtime.h>
#include <cstdint>

#define N_SRC 50000
#define N_DST 50000
#define IN_FEAT 128
#define OUT_FEAT 128

// Device-global scratch (allocation-free).
// INVARIANT: g_neigh and g_deg are all-zero at every kernel_launch entry.
// (Zero-initialized at module load; the GEMM's phase-1 consume-and-reset
//  restores zeros before each call returns.)
__device__ float g_neigh[(size_t)N_DST * IN_FEAT];
__device__ float g_deg[N_DST];

// ---------------------------------------------------------------------------
// Kernel 1: edge aggregation (R5 champion: one warp per edge, vector red.add).
// LTS-bound: 307MB gather reads + 307MB atomic RMW writes.
// ---------------------------------------------------------------------------
__global__ __launch_bounds__(256) void edge_kernel(
    const float* __restrict__ h_s,
    const int* __restrict__ src,
    const int* __restrict__ dst,
    int n_edges)
{
    int warp = (blockIdx.x * blockDim.x + threadIdx.x) >> 5;
    int lane = threadIdx.x & 31;
    if (warp >= n_edges) return;

    int s = __ldg(src + warp);
    int d = __ldg(dst + warp);

    const float4 v = __ldg(reinterpret_cast<const float4*>(h_s + (size_t)s * IN_FEAT) + lane);
    float* p = g_neigh + (size_t)d * IN_FEAT + lane * 4;
    asm volatile("red.global.add.v4.f32 [%0], {%1, %2, %3, %4};"
                 :: "l"(p), "f"(v.x), "f"(v.y), "f"(v.z), "f"(v.w)
                 : "memory");
    if (lane == 0) atomicAdd(g_deg + d, 1.0f);
}

// ---------------------------------------------------------------------------
// Kernel 2: fused mean + concat + Linear via TF32 mma.sync + ldmatrix
// (exact R5 tile structure), with CONSUME-AND-RESET: phase-1 A-tile loads and
// the g_deg read each write zeros back, restoring the entry invariant and
// making a separate zero_kernel unnecessary.
// ---------------------------------------------------------------------------
#define BM 128
#define BK 32
#define KPAD 36   // 144B row stride = 9x16B units -> LDSM rows distinct mod 8

__device__ __forceinline__ uint32_t f2tf32(float v) {
    uint32_t r;
    asm("cvt.rna.tf32.f32 %0, %1;" : "=r"(r) : "f"(v));
    return r;
}

__device__ __forceinline__ void mma_tf32(float c[4],
                                         uint32_t a0, uint32_t a1, uint32_t a2, uint32_t a3,
                                         uint32_t b0, uint32_t b1) {
    asm("mma.sync.aligned.m16n8k8.row.col.f32.tf32.tf32.f32 "
        "{%0,%1,%2,%3}, {%4,%5,%6,%7}, {%8,%9}, {%0,%1,%2,%3};"
        : "+f"(c[0]), "+f"(c[1]), "+f"(c[2]), "+f"(c[3])
        : "r"(a0), "r"(a1), "r"(a2), "r"(a3), "r"(b0), "r"(b1));
}

#define LDSM_X4(r0, r1, r2, r3, addr) \
    asm volatile("ldmatrix.sync.aligned.m8n8.x4.shared.b16 {%0,%1,%2,%3}, [%4];" \
                 : "=r"(r0), "=r"(r1), "=r"(r2), "=r"(r3) : "r"(addr))

__global__ __launch_bounds__(256) void gemm_kernel(
    const float* __restrict__ h_d,
    const float* __restrict__ W,     // [128, 256] row-major
    const float* __restrict__ bias,  // [128]
    float* __restrict__ out)         // [N_DST, 128]
{
    __shared__ uint32_t As[BM][KPAD];
    __shared__ uint32_t Bs[OUT_FEAT][KPAD];
    __shared__ float sInv[BM];

    const int t    = threadIdx.x;
    const int bm   = blockIdx.x * BM;
    const int wid  = t >> 5;
    const int lane = t & 31;
    const int warp_m = wid >> 1;   // 0..3
    const int warp_n = wid & 1;    // 0..1
    const int group  = lane >> 2;  // 0..7
    const int tid4   = lane & 3;   // 0..3

    if (t < BM) {
        int r = bm + t;
        float dg = 1.0f;
        if (r < N_DST) {
            dg = g_deg[r];
            g_deg[r] = 0.0f;       // consume-and-reset (this block is sole reader)
        }
        sInv[t] = 1.0f / fmaxf(dg, 1.0f);
    }

    // ldmatrix per-thread row addresses
    const int lrow = lane & 7;
    const int lmat = lane >> 3;
    uint32_t as_base = (uint32_t)__cvta_generic_to_shared(&As[0][0]);
    uint32_t bs_base = (uint32_t)__cvta_generic_to_shared(&Bs[0][0]);

    uint32_t aAddr[2];
    #pragma unroll
    for (int mt = 0; mt < 2; ++mt) {
        int row = warp_m * 32 + mt * 16 + (lmat & 1) * 8 + lrow;
        int col = (lmat >> 1) * 4;
        aAddr[mt] = as_base + (row * KPAD + col) * 4;
    }
    uint32_t bAddr[4];
    #pragma unroll
    for (int p = 0; p < 4; ++p) {
        int row = warp_n * 64 + p * 16 + (lmat >> 1) * 8 + lrow;
        int col = (lmat & 1) * 4;
        bAddr[p] = bs_base + (row * KPAD + col) * 4;
    }

    float acc[2][8][4];
    #pragma unroll
    for (int mt = 0; mt < 2; ++mt)
        #pragma unroll
        for (int nt = 0; nt < 8; ++nt)
            #pragma unroll
            for (int c = 0; c < 4; ++c) acc[mt][nt][c] = 0.f;

    #pragma unroll 1
    for (int ph = 0; ph < 2; ++ph) {
        const float* __restrict__ A = ph ? g_neigh : h_d;
        #pragma unroll 1
        for (int k0 = 0; k0 < IN_FEAT; k0 += BK) {
            __syncthreads();   // prev compute done; sInv ready (iter 0)

            // --- A tile: 128 rows x 32 cols (1/deg folded in on phase 1;
            //     phase 1 also zeros each consumed g_neigh chunk: each
            //     (row, 16B-chunk) is read exactly once, by this thread).
            #pragma unroll
            for (int i = 0; i < 4; ++i) {
                int idx = t + i * 256;          // 0..1023
                int row = idx >> 3;             // 0..127
                int c4  = (idx & 7) * 4;        // 0..28
                int gr  = bm + row;
                float4 v = make_float4(0.f, 0.f, 0.f, 0.f);
                if (gr < N_DST) {
                    v = __ldg(reinterpret_cast<const float4*>(A + (size_t)gr * IN_FEAT + k0 + c4));
                    if (ph) {
                        *reinterpret_cast<float4*>(g_neigh + (size_t)gr * IN_FEAT + k0 + c4) =
                            make_float4(0.f, 0.f, 0.f, 0.f);
                    }
                }
                float s = ph ? sInv[row] : 1.0f;
                As[row][c4 + 0] = f2tf32(v.x * s);
                As[row][c4 + 1] = f2tf32(v.y * s);
                As[row][c4 + 2] = f2tf32(v.z * s);
                As[row][c4 + 3] = f2tf32(v.w * s);
            }
            // --- B tile: Bs[o][k] = W[o][ph*128 + k0 + k]
            #pragma unroll
            for (int i = 0; i < 4; ++i) {
                int idx = t + i * 256;
                int o   = idx >> 3;
                int c4  = (idx & 7) * 4;
                float4 v = __ldg(reinterpret_cast<const float4*>(
                    W + (size_t)o * (2 * IN_FEAT) + ph * IN_FEAT + k0 + c4));
                Bs[o][c4 + 0] = f2tf32(v.x);
                Bs[o][c4 + 1] = f2tf32(v.y);
                Bs[o][c4 + 2] = f2tf32(v.z);
                Bs[o][c4 + 3] = f2tf32(v.w);
            }
            __syncthreads();

            // --- compute: 4 k8-steps, fragments via LDSM.x4
            #pragma unroll
            for (int kk = 0; kk < BK; kk += 8) {
                uint32_t af[2][4], bf[8][2];
                #pragma unroll
                for (int mt = 0; mt < 2; ++mt)
                    LDSM_X4(af[mt][0], af[mt][1], af[mt][2], af[mt][3],
                            aAddr[mt] + kk * 4);
                #pragma unroll
                for (int p = 0; p < 4; ++p)
                    LDSM_X4(bf[2 * p][0], bf[2 * p][1], bf[2 * p + 1][0], bf[2 * p + 1][1],
                            bAddr[p] + kk * 4);
                #pragma unroll
                for (int mt = 0; mt < 2; ++mt)
                    #pragma unroll
                    for (int nt = 0; nt < 8; ++nt)
                        mma_tf32(acc[mt][nt], af[mt][0], af[mt][1], af[mt][2], af[mt][3],
                                 bf[nt][0], bf[nt][1]);
            }
        }
    }

    // --- epilogue: bias + store ---
    #pragma unroll
    for (int mt = 0; mt < 2; ++mt) {
        int r0 = bm + warp_m * 32 + mt * 16 + group;
        #pragma unroll
        for (int nt = 0; nt < 8; ++nt) {
            int c = warp_n * 64 + nt * 8 + tid4 * 2;
            float b0 = __ldg(bias + c);
            float b1 = __ldg(bias + c + 1);
            if (r0 < N_DST) {
                float2 v = make_float2(acc[mt][nt][0] + b0, acc[mt][nt][1] + b1);
                *reinterpret_cast<float2*>(out + (size_t)r0 * OUT_FEAT + c) = v;
            }
            int r1 = r0 + 8;
            if (r1 < N_DST) {
                float2 v = make_float2(acc[mt][nt][2] + b0, acc[mt][nt][3] + b1);
                *reinterpret_cast<float2*>(out + (size_t)r1 * OUT_FEAT + c) = v;
            }
        }
    }
}

// ---------------------------------------------------------------------------
extern "C" void kernel_launch(void* const* d_in, const int* in_sizes, int n_in,
                              void* d_out, int out_size)
{
    const float* h_s = (const float*)d_in[0];
    const float* h_d = (const float*)d_in[1];
    const int*   src = (const int*)d_in[2];
    const int*   dst = (const int*)d_in[3];
    const float* W   = (const float*)d_in[4];
    const float* b   = (const float*)d_in[5];
    float* out = (float*)d_out;

    const int n_edges = in_sizes[2];

    int blocks = (n_edges * 32 + 255) / 256;
    edge_kernel<<<blocks, 256>>>(h_s, src, dst, n_edges);

    int gblocks = (N_DST + BM - 1) / BM;              // 391
    gemm_kernel<<<gblocks, 256>>>(h_d, W, b, out);
}

// round 10
// speedup vs baseline: 2.1695x; 1.3181x over previous
#include <cuda_runtime.h>
#include <cstdint>

#define N_SRC 50000
#define N_DST 50000
#define IN_FEAT 128
#define OUT_FEAT 128

// Device-global scratch (allocation-free).
__device__ float g_neigh[(size_t)N_DST * IN_FEAT];
__device__ float g_deg[N_DST];

// ---------------------------------------------------------------------------
// Kernel 1: zero the accumulators (exact R5)
// ---------------------------------------------------------------------------
__global__ __launch_bounds__(256) void zero_kernel() {
    const size_t n4 = (size_t)N_DST * IN_FEAT / 4;
    size_t i = (size_t)blockIdx.x * blockDim.x + threadIdx.x;
    size_t stride = (size_t)gridDim.x * blockDim.x;
    float4* p = reinterpret_cast<float4*>(g_neigh);
    for (size_t j = i; j < n4; j += stride)
        p[j] = make_float4(0.f, 0.f, 0.f, 0.f);
    for (size_t j = i; j < N_DST; j += stride)
        g_deg[j] = 0.f;
}

// ---------------------------------------------------------------------------
// Kernel 2: edge aggregation (exact R5 champion: one warp per edge).
// ---------------------------------------------------------------------------
__global__ __launch_bounds__(256) void edge_kernel(
    const float* __restrict__ h_s,
    const int* __restrict__ src,
    const int* __restrict__ dst,
    int n_edges)
{
    int warp = (blockIdx.x * blockDim.x + threadIdx.x) >> 5;
    int lane = threadIdx.x & 31;
    if (warp >= n_edges) return;

    int s = __ldg(src + warp);
    int d = __ldg(dst + warp);

    const float4 v = __ldg(reinterpret_cast<const float4*>(h_s + (size_t)s * IN_FEAT) + lane);
    float* p = g_neigh + (size_t)d * IN_FEAT + lane * 4;
    asm volatile("red.global.add.v4.f32 [%0], {%1, %2, %3, %4};"
                 :: "l"(p), "f"(v.x), "f"(v.y), "f"(v.z), "f"(v.w)
                 : "memory");
    if (lane == 0) atomicAdd(g_deg + d, 1.0f);
}

// ---------------------------------------------------------------------------
// Kernel 3: fused mean + concat + Linear. TF32 mma.sync + ldmatrix, with a
// 2-stage cp.async GMEM->SMEM pipeline (no register staging).
//   Tiles 0..3: A = g_neigh, W cols [128,256). Tiles 4..7: A = h_d, W cols [0,128).
//   acc *= sInv at the tile-3/4 boundary (replaces per-element A scaling).
// ---------------------------------------------------------------------------
#define BM 128
#define BK 32
#define KPAD 36                       // 144B row stride: 16B-aligned, LDSM conflict-free
#define TILE_WORDS (BM * KPAD)        // 4608 words
#define TILE_BYTES (TILE_WORDS * 4)   // 18432 B
#define SMEM_BYTES (4 * TILE_BYTES)   // A0,A1,B0,B1 = 73728 B

__device__ __forceinline__ uint32_t f2tf32(float v) {
    uint32_t r;
    asm("cvt.rna.tf32.f32 %0, %1;" : "=r"(r) : "f"(v));
    return r;
}
__device__ __forceinline__ uint32_t bits2tf32(uint32_t x) {
    return f2tf32(__uint_as_float(x));
}

__device__ __forceinline__ void mma_tf32(float c[4],
                                         uint32_t a0, uint32_t a1, uint32_t a2, uint32_t a3,
                                         uint32_t b0, uint32_t b1) {
    asm("mma.sync.aligned.m16n8k8.row.col.f32.tf32.tf32.f32 "
        "{%0,%1,%2,%3}, {%4,%5,%6,%7}, {%8,%9}, {%0,%1,%2,%3};"
        : "+f"(c[0]), "+f"(c[1]), "+f"(c[2]), "+f"(c[3])
        : "r"(a0), "r"(a1), "r"(a2), "r"(a3), "r"(b0), "r"(b1));
}

#define LDSM_X4(r0, r1, r2, r3, addr) \
    asm volatile("ldmatrix.sync.aligned.m8n8.x4.shared.b16 {%0,%1,%2,%3}, [%4];" \
                 : "=r"(r0), "=r"(r1), "=r"(r2), "=r"(r3) : "r"(addr))

#define CP_ASYNC16(smem_u32, gptr, szr) \
    asm volatile("cp.async.ca.shared.global [%0], [%1], 16, %2;" \
                 :: "r"(smem_u32), "l"(gptr), "r"(szr) : "memory")
#define CP_COMMIT()  asm volatile("cp.async.commit_group;" ::: "memory")
#define CP_WAIT0()   asm volatile("cp.async.wait_group 0;" ::: "memory")

__global__ __launch_bounds__(256, 2) void gemm_kernel(
    const float* __restrict__ h_d,
    const float* __restrict__ W,     // [128, 256] row-major
    const float* __restrict__ bias,  // [128]
    float* __restrict__ out)         // [N_DST, 128]
{
    extern __shared__ uint32_t dynsmem[];
    __shared__ float sInv[BM];

    const int t    = threadIdx.x;
    const int bm   = blockIdx.x * BM;
    const int wid  = t >> 5;
    const int lane = t & 31;
    const int warp_m = wid >> 1;   // 0..3
    const int warp_n = wid & 1;    // 0..1
    const int group  = lane >> 2;  // 0..7
    const int tid4   = lane & 3;   // 0..3

    if (t < BM) {
        int r = bm + t;
        float dg = (r < N_DST) ? g_deg[r] : 1.0f;
        sInv[t] = 1.0f / fmaxf(dg, 1.0f);
    }

    // ---- per-thread cp.async coordinates: 4 chunks of 16B per tile (A and B)
    const int ld_row0 = t >> 3;            // 0..31, + 32*i
    const int ld_c4   = (t & 7) * 4;       // word offset 0..28 (16B-aligned)

    uint32_t smem_base = (uint32_t)__cvta_generic_to_shared(dynsmem);
    // store addresses for buffer 0; buffer 1 = +TILE_BYTES
    uint32_t aSt[4], bSt[4];
    #pragma unroll
    for (int i = 0; i < 4; ++i) {
        int row = ld_row0 + i * 32;
        aSt[i] = smem_base + (row * KPAD + ld_c4) * 4;
        bSt[i] = smem_base + 2 * TILE_BYTES + (row * KPAD + ld_c4) * 4;
    }

    // ---- ldmatrix per-thread addresses (buffer 0 bases)
    const int lrow = lane & 7;
    const int lmat = lane >> 3;
    uint32_t aAddr[2];
    #pragma unroll
    for (int mt = 0; mt < 2; ++mt) {
        int row = warp_m * 32 + mt * 16 + (lmat & 1) * 8 + lrow;
        int col = (lmat >> 1) * 4;
        aAddr[mt] = smem_base + (row * KPAD + col) * 4;
    }
    uint32_t bAddr[4];
    #pragma unroll
    for (int p = 0; p < 4; ++p) {
        int row = warp_n * 64 + p * 16 + (lmat >> 1) * 8 + lrow;
        int col = (lmat & 1) * 4;
        bAddr[p] = smem_base + 2 * TILE_BYTES + (row * KPAD + col) * 4;
    }

    float acc[2][8][4];
    #pragma unroll
    for (int mt = 0; mt < 2; ++mt)
        #pragma unroll
        for (int nt = 0; nt < 8; ++nt)
            #pragma unroll
            for (int c = 0; c < 4; ++c) acc[mt][nt][c] = 0.f;

    // ---- tile prefetch: tile it (0..7). it<4: neigh phase; else h_d phase.
    auto prefetch = [&](int it) {
        const float* __restrict__ A = (it < 4) ? g_neigh : h_d;
        const int wofs = (it < 4) ? IN_FEAT : 0;     // W column offset of this phase
        const int k0 = (it & 3) * BK;
        const uint32_t boff = (it & 1) * TILE_BYTES;
        #pragma unroll
        for (int i = 0; i < 4; ++i) {
            int row = ld_row0 + i * 32;
            int gr  = bm + row;
            int ok  = (gr < N_DST);
            int gra = ok ? gr : 0;
            const float* gp = A + (size_t)gra * IN_FEAT + k0 + ld_c4;
            int sz = ok ? 16 : 0;                    // src-size 0 -> zero-fill
            CP_ASYNC16(aSt[i] + boff, gp, sz);
        }
        #pragma unroll
        for (int i = 0; i < 4; ++i) {
            int o = ld_row0 + i * 32;                // 0..127, always valid
            const float* gp = W + (size_t)o * (2 * IN_FEAT) + wofs + k0 + ld_c4;
            int sz16 = 16;
            CP_ASYNC16(bSt[i] + boff, gp, sz16);
        }
        CP_COMMIT();
    };

    // ---- prologue
    prefetch(0);

    // ---- main pipeline: 8 tiles, one sync each
    #pragma unroll 1
    for (int it = 0; it < 8; ++it) {
        CP_WAIT0();          // tile it landed in buf[it&1]
        __syncthreads();     // visible to all; buf[(it+1)&1] free (last read it-1)

        if (it < 7) prefetch(it + 1);

        if (it == 4) {
            // phase boundary: scale the neigh-phase partial sums by 1/deg
            #pragma unroll
            for (int mt = 0; mt < 2; ++mt) {
                int row0 = warp_m * 32 + mt * 16 + group;
                float s0 = sInv[row0];
                float s1 = sInv[row0 + 8];
                #pragma unroll
                for (int nt = 0; nt < 8; ++nt) {
                    acc[mt][nt][0] *= s0;
                    acc[mt][nt][1] *= s0;
                    acc[mt][nt][2] *= s1;
                    acc[mt][nt][3] *= s1;
                }
            }
        }

        const uint32_t boff = (it & 1) * TILE_BYTES;
        #pragma unroll
        for (int kk = 0; kk < BK; kk += 8) {
            uint32_t af[2][4], bf[8][2];
            #pragma unroll
            for (int mt = 0; mt < 2; ++mt)
                LDSM_X4(af[mt][0], af[mt][1], af[mt][2], af[mt][3],
                        aAddr[mt] + boff + kk * 4);
            #pragma unroll
            for (int p = 0; p < 4; ++p)
                LDSM_X4(bf[2 * p][0], bf[2 * p][1], bf[2 * p + 1][0], bf[2 * p + 1][1],
                        bAddr[p] + boff + kk * 4);
            // raw fp32 -> tf32 (RNA) on fragments
            #pragma unroll
            for (int mt = 0; mt < 2; ++mt)
                #pragma unroll
                for (int j = 0; j < 4; ++j) af[mt][j] = bits2tf32(af[mt][j]);
            #pragma unroll
            for (int nt = 0; nt < 8; ++nt) {
                bf[nt][0] = bits2tf32(bf[nt][0]);
                bf[nt][1] = bits2tf32(bf[nt][1]);
            }
            #pragma unroll
            for (int mt = 0; mt < 2; ++mt)
                #pragma unroll
                for (int nt = 0; nt < 8; ++nt)
                    mma_tf32(acc[mt][nt], af[mt][0], af[mt][1], af[mt][2], af[mt][3],
                             bf[nt][0], bf[nt][1]);
        }
    }

    // ---- epilogue: bias + store ----
    #pragma unroll
    for (int mt = 0; mt < 2; ++mt) {
        int r0 = bm + warp_m * 32 + mt * 16 + group;
        #pragma unroll
        for (int nt = 0; nt < 8; ++nt) {
            int c = warp_n * 64 + nt * 8 + tid4 * 2;
            float b0 = __ldg(bias + c);
            float b1 = __ldg(bias + c + 1);
            if (r0 < N_DST) {
                float2 v = make_float2(acc[mt][nt][0] + b0, acc[mt][nt][1] + b1);
                *reinterpret_cast<float2*>(out + (size_t)r0 * OUT_FEAT + c) = v;
            }
            int r1 = r0 + 8;
            if (r1 < N_DST) {
                float2 v = make_float2(acc[mt][nt][2] + b0, acc[mt][nt][3] + b1);
                *reinterpret_cast<float2*>(out + (size_t)r1 * OUT_FEAT + c) = v;
            }
        }
    }
}

// ---------------------------------------------------------------------------
extern "C" void kernel_launch(void* const* d_in, const int* in_sizes, int n_in,
                              void* d_out, int out_size)
{
    const float* h_s = (const float*)d_in[0];
    const float* h_d = (const float*)d_in[1];
    const int*   src = (const int*)d_in[2];
    const int*   dst = (const int*)d_in[3];
    const float* W   = (const float*)d_in[4];
    const float* b   = (const float*)d_in[5];
    float* out = (float*)d_out;

    const int n_edges = in_sizes[2];

    // Host-side attribute set: capture-time only, zero replay cost.
    cudaFuncSetAttribute(gemm_kernel,
                         cudaFuncAttributeMaxDynamicSharedMemorySize, SMEM_BYTES);

    zero_kernel<<<1184, 256>>>();

    int blocks = (n_edges * 32 + 255) / 256;
    edge_kernel<<<blocks, 256>>>(h_s, src, dst, n_edges);

    int gblocks = (N_DST + BM - 1) / BM;              // 391
    gemm_kernel<<<gblocks, 256, SMEM_BYTES>>>(h_d, W, b, out);
}

// round 11
// speedup vs baseline: 2.2266x; 1.0263x over previous
#include <cuda_runtime.h>
#include <cstdint>

#define N_SRC 50000
#define N_DST 50000
#define IN_FEAT 128
#define OUT_FEAT 128

// Device-global scratch (allocation-free).
__device__ float    g_neigh[(size_t)N_DST * IN_FEAT];
__device__ float    g_deg[N_DST];
__device__ uint32_t g_Wtf[OUT_FEAT * 2 * IN_FEAT];   // W pre-converted to tf32 (RNA)

__device__ __forceinline__ uint32_t f2tf32(float v) {
    uint32_t r;
    asm("cvt.rna.tf32.f32 %0, %1;" : "=r"(r) : "f"(v));
    return r;
}
__device__ __forceinline__ uint32_t bits2tf32(uint32_t x) {
    return f2tf32(__uint_as_float(x));
}

// ---------------------------------------------------------------------------
// Kernel 1: zero the accumulators + pre-convert W to tf32.
// ---------------------------------------------------------------------------
__global__ __launch_bounds__(256) void zero_kernel(const float* __restrict__ W) {
    const size_t n4 = (size_t)N_DST * IN_FEAT / 4;
    size_t i = (size_t)blockIdx.x * blockDim.x + threadIdx.x;
    size_t stride = (size_t)gridDim.x * blockDim.x;
    float4* p = reinterpret_cast<float4*>(g_neigh);
    for (size_t j = i; j < n4; j += stride)
        p[j] = make_float4(0.f, 0.f, 0.f, 0.f);
    for (size_t j = i; j < N_DST; j += stride)
        g_deg[j] = 0.f;
    // W: 32768 elements, vectorized convert
    const size_t nw4 = (size_t)OUT_FEAT * 2 * IN_FEAT / 4;
    const float4* w4 = reinterpret_cast<const float4*>(W);
    uint4* o4 = reinterpret_cast<uint4*>(g_Wtf);
    for (size_t j = i; j < nw4; j += stride) {
        float4 v = __ldg(w4 + j);
        uint4 u;
        u.x = f2tf32(v.x); u.y = f2tf32(v.y);
        u.z = f2tf32(v.z); u.w = f2tf32(v.w);
        o4[j] = u;
    }
}

// ---------------------------------------------------------------------------
// Kernel 2: edge aggregation (exact R5 champion: one warp per edge).
// At the LTS roofline: 307MB gather reads + 307MB atomic RMW writes.
// ---------------------------------------------------------------------------
__global__ __launch_bounds__(256) void edge_kernel(
    const float* __restrict__ h_s,
    const int* __restrict__ src,
    const int* __restrict__ dst,
    int n_edges)
{
    int warp = (blockIdx.x * blockDim.x + threadIdx.x) >> 5;
    int lane = threadIdx.x & 31;
    if (warp >= n_edges) return;

    int s = __ldg(src + warp);
    int d = __ldg(dst + warp);

    const float4 v = __ldg(reinterpret_cast<const float4*>(h_s + (size_t)s * IN_FEAT) + lane);
    float* p = g_neigh + (size_t)d * IN_FEAT + lane * 4;
    asm volatile("red.global.add.v4.f32 [%0], {%1, %2, %3, %4};"
                 :: "l"(p), "f"(v.x), "f"(v.y), "f"(v.z), "f"(v.w)
                 : "memory");
    if (lane == 0) atomicAdd(g_deg + d, 1.0f);
}

// ---------------------------------------------------------------------------
// Kernel 3: fused mean + concat + Linear. TF32 mma.sync + ldmatrix + 2-stage
// cp.async pipeline. B tiles come pre-converted from g_Wtf (no B-side CVT);
// A fragments are converted post-ldmatrix (32 CVT/tile/warp, under the floor).
//   Tiles 0..3: A = g_neigh, Wtf cols [128,256). Tiles 4..7: A = h_d, cols [0,128).
//   acc *= 1/deg at the tile-3/4 boundary.
// ---------------------------------------------------------------------------
#define BM 128
#define BK 32
#define KPAD 36                       // 144B row stride: 16B-aligned, LDSM conflict-free
#define TILE_WORDS (BM * KPAD)        // 4608 words
#define TILE_BYTES (TILE_WORDS * 4)   // 18432 B
#define SMEM_BYTES (4 * TILE_BYTES)   // A0,A1,B0,B1 = 73728 B

__device__ __forceinline__ void mma_tf32(float c[4],
                                         uint32_t a0, uint32_t a1, uint32_t a2, uint32_t a3,
                                         uint32_t b0, uint32_t b1) {
    asm("mma.sync.aligned.m16n8k8.row.col.f32.tf32.tf32.f32 "
        "{%0,%1,%2,%3}, {%4,%5,%6,%7}, {%8,%9}, {%0,%1,%2,%3};"
        : "+f"(c[0]), "+f"(c[1]), "+f"(c[2]), "+f"(c[3])
        : "r"(a0), "r"(a1), "r"(a2), "r"(a3), "r"(b0), "r"(b1));
}

#define LDSM_X4(r0, r1, r2, r3, addr) \
    asm volatile("ldmatrix.sync.aligned.m8n8.x4.shared.b16 {%0,%1,%2,%3}, [%4];" \
                 : "=r"(r0), "=r"(r1), "=r"(r2), "=r"(r3) : "r"(addr))

#define CP_ASYNC16(smem_u32, gptr, szr) \
    asm volatile("cp.async.ca.shared.global [%0], [%1], 16, %2;" \
                 :: "r"(smem_u32), "l"(gptr), "r"(szr) : "memory")
#define CP_COMMIT()  asm volatile("cp.async.commit_group;" ::: "memory")
#define CP_WAIT0()   asm volatile("cp.async.wait_group 0;" ::: "memory")

__global__ __launch_bounds__(256, 2) void gemm_kernel(
    const float* __restrict__ h_d,
    const float* __restrict__ bias,  // [128]
    float* __restrict__ out)         // [N_DST, 128]
{
    extern __shared__ uint32_t dynsmem[];
    __shared__ float sInv[BM];

    const int t    = threadIdx.x;
    const int bm   = blockIdx.x * BM;
    const int wid  = t >> 5;
    const int lane = t & 31;
    const int warp_m = wid >> 1;   // 0..3
    const int warp_n = wid & 1;    // 0..1
    const int group  = lane >> 2;  // 0..7
    const int tid4   = lane & 3;   // 0..3

    if (t < BM) {
        int r = bm + t;
        float dg = (r < N_DST) ? g_deg[r] : 1.0f;
        sInv[t] = 1.0f / fmaxf(dg, 1.0f);
    }

    // ---- per-thread cp.async coordinates: 4 chunks of 16B per tile (A and B)
    const int ld_row0 = t >> 3;            // 0..31, + 32*i
    const int ld_c4   = (t & 7) * 4;       // word offset 0..28 (16B-aligned)

    uint32_t smem_base = (uint32_t)__cvta_generic_to_shared(dynsmem);
    uint32_t aSt[4], bSt[4];
    #pragma unroll
    for (int i = 0; i < 4; ++i) {
        int row = ld_row0 + i * 32;
        aSt[i] = smem_base + (row * KPAD + ld_c4) * 4;
        bSt[i] = smem_base + 2 * TILE_BYTES + (row * KPAD + ld_c4) * 4;
    }

    // ---- ldmatrix per-thread addresses (buffer 0 bases)
    const int lrow = lane & 7;
    const int lmat = lane >> 3;
    uint32_t aAddr[2];
    #pragma unroll
    for (int mt = 0; mt < 2; ++mt) {
        int row = warp_m * 32 + mt * 16 + (lmat & 1) * 8 + lrow;
        int col = (lmat >> 1) * 4;
        aAddr[mt] = smem_base + (row * KPAD + col) * 4;
    }
    uint32_t bAddr[4];
    #pragma unroll
    for (int p = 0; p < 4; ++p) {
        int row = warp_n * 64 + p * 16 + (lmat >> 1) * 8 + lrow;
        int col = (lmat & 1) * 4;
        bAddr[p] = smem_base + 2 * TILE_BYTES + (row * KPAD + col) * 4;
    }

    float acc[2][8][4];
    #pragma unroll
    for (int mt = 0; mt < 2; ++mt)
        #pragma unroll
        for (int nt = 0; nt < 8; ++nt)
            #pragma unroll
            for (int c = 0; c < 4; ++c) acc[mt][nt][c] = 0.f;

    // ---- tile prefetch: tile it (0..7). it<4: neigh phase; else h_d phase.
    auto prefetch = [&](int it) {
        const float* __restrict__ A = (it < 4) ? g_neigh : h_d;
        const int wofs = (it < 4) ? IN_FEAT : 0;
        const int k0 = (it & 3) * BK;
        const uint32_t boff = (it & 1) * TILE_BYTES;
        #pragma unroll
        for (int i = 0; i < 4; ++i) {
            int row = ld_row0 + i * 32;
            int gr  = bm + row;
            int ok  = (gr < N_DST);
            int gra = ok ? gr : 0;
            const float* gp = A + (size_t)gra * IN_FEAT + k0 + ld_c4;
            int sz = ok ? 16 : 0;                    // src-size 0 -> zero-fill
            CP_ASYNC16(aSt[i] + boff, gp, sz);
        }
        #pragma unroll
        for (int i = 0; i < 4; ++i) {
            int o = ld_row0 + i * 32;                // 0..127, always valid
            const uint32_t* gp = g_Wtf + (size_t)o * (2 * IN_FEAT) + wofs + k0 + ld_c4;
            int sz16 = 16;
            CP_ASYNC16(bSt[i] + boff, gp, sz16);
        }
        CP_COMMIT();
    };

    // ---- prologue
    prefetch(0);

    // ---- main pipeline: 8 tiles, one sync each
    #pragma unroll 1
    for (int it = 0; it < 8; ++it) {
        CP_WAIT0();          // tile it landed in buf[it&1]
        __syncthreads();     // visible to all; buf[(it+1)&1] free (last read it-1)

        if (it < 7) prefetch(it + 1);

        if (it == 4) {
            // phase boundary: scale the neigh-phase partial sums by 1/deg
            #pragma unroll
            for (int mt = 0; mt < 2; ++mt) {
                int row0 = warp_m * 32 + mt * 16 + group;
                float s0 = sInv[row0];
                float s1 = sInv[row0 + 8];
                #pragma unroll
                for (int nt = 0; nt < 8; ++nt) {
                    acc[mt][nt][0] *= s0;
                    acc[mt][nt][1] *= s0;
                    acc[mt][nt][2] *= s1;
                    acc[mt][nt][3] *= s1;
                }
            }
        }

        const uint32_t boff = (it & 1) * TILE_BYTES;
        #pragma unroll
        for (int kk = 0; kk < BK; kk += 8) {
            uint32_t af[2][4], bf[8][2];
            #pragma unroll
            for (int mt = 0; mt < 2; ++mt)
                LDSM_X4(af[mt][0], af[mt][1], af[mt][2], af[mt][3],
                        aAddr[mt] + boff + kk * 4);
            #pragma unroll
            for (int p = 0; p < 4; ++p)
                LDSM_X4(bf[2 * p][0], bf[2 * p][1], bf[2 * p + 1][0], bf[2 * p + 1][1],
                        bAddr[p] + boff + kk * 4);
            // A fragments: raw fp32 -> tf32 (RNA). B is pre-converted.
            #pragma unroll
            for (int mt = 0; mt < 2; ++mt)
                #pragma unroll
                for (int j = 0; j < 4; ++j) af[mt][j] = bits2tf32(af[mt][j]);
            #pragma unroll
            for (int mt = 0; mt < 2; ++mt)
                #pragma unroll
                for (int nt = 0; nt < 8; ++nt)
                    mma_tf32(acc[mt][nt], af[mt][0], af[mt][1], af[mt][2], af[mt][3],
                             bf[nt][0], bf[nt][1]);
        }
    }

    // ---- epilogue: bias + store ----
    #pragma unroll
    for (int mt = 0; mt < 2; ++mt) {
        int r0 = bm + warp_m * 32 + mt * 16 + group;
        #pragma unroll
        for (int nt = 0; nt < 8; ++nt) {
            int c = warp_n * 64 + nt * 8 + tid4 * 2;
            float b0 = __ldg(bias + c);
            float b1 = __ldg(bias + c + 1);
            if (r0 < N_DST) {
                float2 v = make_float2(acc[mt][nt][0] + b0, acc[mt][nt][1] + b1);
                *reinterpret_cast<float2*>(out + (size_t)r0 * OUT_FEAT + c) = v;
            }
            int r1 = r0 + 8;
            if (r1 < N_DST) {
                float2 v = make_float2(acc[mt][nt][2] + b0, acc[mt][nt][3] + b1);
                *reinterpret_cast<float2*>(out + (size_t)r1 * OUT_FEAT + c) = v;
            }
        }
    }
}

// ---------------------------------------------------------------------------
extern "C" void kernel_launch(void* const* d_in, const int* in_sizes, int n_in,
                              void* d_out, int out_size)
{
    const float* h_s = (const float*)d_in[0];
    const float* h_d = (const float*)d_in[1];
    const int*   src = (const int*)d_in[2];
    const int*   dst = (const int*)d_in[3];
    const float* W   = (const float*)d_in[4];
    const float* b   = (const float*)d_in[5];
    float* out = (float*)d_out;

    const int n_edges = in_sizes[2];

    // Host-side attribute set: capture-time only, zero replay cost.
    cudaFuncSetAttribute(gemm_kernel,
                         cudaFuncAttributeMaxDynamicSharedMemorySize, SMEM_BYTES);

    zero_kernel<<<1184, 256>>>(W);

    int blocks = (n_edges * 32 + 255) / 256;
    edge_kernel<<<blocks, 256>>>(h_s, src, dst, n_edges);

    int gblocks = (N_DST + BM - 1) / BM;              // 391
    gemm_kernel<<<gblocks, 256, SMEM_BYTES>>>(h_d, b, out);
}